// round 10
// baseline (speedup 1.0000x reference)
#include <cuda_runtime.h>
#include <cuda_fp16.h>
#include <cstdint>

// ---------------- problem constants ----------------
#define HH 80
#define WW 120
#define TT 12
#define FF 32
#define NPX (HH*WW)

#define TILY 20
#define TILX 12
#define NTILES 40        // (80/20) * (120/12)
#define NTHREADS 640     // 20 warps

// staged region: tile +-2  -> 24 x 16 px per batch
#define SGY 24
#define SGX 16
#define NSTG 384
#define PXB 112          // bytes per staged pixel: [h 32f16 | x 8f16 | pad]

// gate ring: tile +-1 -> 22 x 14 = 308 px (padded to 320 = 20 strips/batch)
#define RINGW 14
#define NRING 308
#define NINT 240         // interior 20*12

#define KW 440           // f16 per weight row (432 = 9*48 + pad)
#define WRB 880

#define SM_HALO_B (2*NSTG*PXB)                 // 86016
#define SM_WA_B   (64*WRB)                     // 56320
#define SM_WB_B   (32*WRB)                     // 28160
#define SM_Z_OFF  (SM_HALO_B+SM_WA_B+SM_WB_B)  // 170496
#define SM_Z_B    (2*NINT*32*4)                // 61440 (fp32 z)
#define SM_TOTAL  (SM_Z_OFF+SM_Z_B)            // 231936 (< 227KB cap)

// ---------------- global scratch ----------------
__device__ __half g_wAh[2*64*KW];
__device__ __half g_wBh[2*32*KW];
__device__ float  g_h  [2*2*NPX*FF];     // fp32 state (exact bypass)
__device__ __half g_hf [2*2*NPX*FF];     // f16 mirror (conv operand)
__device__ __half g_xf8[2*TT*NPX*8];     // x preconverted (6 + 2 zeros)

// ---------------- helpers ----------------
__device__ __forceinline__ uint32_t smem_u32(const void* p) {
    uint32_t a;
    asm("{ .reg .u64 t; cvta.to.shared.u64 t, %1; cvt.u32.u64 %0, t; }" : "=r"(a) : "l"(p));
    return a;
}
__device__ __forceinline__ float sigm(float v) {
    return __fdividef(1.0f, 1.0f + __expf(-v));
}
__device__ __forceinline__ float ftanh(float v) {
    float e = __expf(-2.0f * v);
    return __fdividef(1.0f - e, 1.0f + e);
}
__device__ __forceinline__ void ldm_x4(uint32_t& r0, uint32_t& r1, uint32_t& r2, uint32_t& r3,
                                       uint32_t addr) {
    asm volatile("ldmatrix.sync.aligned.m8n8.x4.shared.b16 {%0,%1,%2,%3}, [%4];"
                 : "=r"(r0), "=r"(r1), "=r"(r2), "=r"(r3) : "r"(addr));
}
__device__ __forceinline__ void mma16816(float* c,
                                         uint32_t a0, uint32_t a1, uint32_t a2, uint32_t a3,
                                         uint32_t b0, uint32_t b1) {
    asm volatile("mma.sync.aligned.m16n8k16.row.col.f32.f16.f16.f32 "
                 "{%0,%1,%2,%3}, {%4,%5,%6,%7}, {%8,%9}, {%0,%1,%2,%3};"
                 : "+f"(c[0]), "+f"(c[1]), "+f"(c[2]), "+f"(c[3])
                 : "r"(a0), "r"(a1), "r"(a2), "r"(a3), "r"(b0), "r"(b1));
}

// ---------------- one-time packs (unchanged layouts) ----------------
__global__ void pack_kernel(const float* __restrict__ WxF, const float* __restrict__ WzrF,
                            const float* __restrict__ WhF,
                            const float* __restrict__ WxB, const float* __restrict__ WzrB,
                            const float* __restrict__ WhB)
{
    const int TOT = 2*96*KW;
    for (int i = blockIdx.x*blockDim.x + threadIdx.x; i < TOT; i += gridDim.x*blockDim.x) {
        int dir = i / (96*KW); int r = i - dir*(96*KW);
        int n96 = r / KW;      int k = r - n96*KW;
        float v = 0.0f;
        if (k < 432) {
            int tap = k / 48, c = k - tap*48;
            const float* Wx  = dir ? WxB  : WxF;
            const float* Wzr = dir ? WzrB : WzrF;
            const float* Wh  = dir ? WhB  : WhF;
            if (c < 32) {
                if (n96 < 64) v = Wzr[(tap*32 + c)*64 + n96];
                else          v = Wh [(tap*32 + c)*32 + (n96 - 64)];
            } else if (c < 38) {
                v = Wx[(tap*6 + (c - 32))*96 + n96];
            }
        }
        __half hv = __float2half_rn(v);
        if (n96 < 64) g_wAh[(dir*64 + n96)*KW + k]        = hv;
        else          g_wBh[(dir*32 + (n96 - 64))*KW + k] = hv;
    }
}

__global__ void convert_x_kernel(const float* __restrict__ x) {
    const int n = 2*TT*NPX;
    for (int p = blockIdx.x*blockDim.x + threadIdx.x; p < n; p += gridDim.x*blockDim.x) {
        const float* src = x + (size_t)p*6;
        __half2 h0 = __floats2half2_rn(src[0], src[1]);
        __half2 h1 = __floats2half2_rn(src[2], src[3]);
        __half2 h2 = __floats2half2_rn(src[4], src[5]);
        uint4 v;
        v.x = *(uint32_t*)&h0; v.y = *(uint32_t*)&h1; v.z = *(uint32_t*)&h2; v.w = 0u;
        *(uint4*)(g_xf8 + (size_t)p*8) = v;
    }
}

__global__ void zero_h_kernel() {
    const int n = 2*2*NPX*FF;
    for (int i = blockIdx.x*blockDim.x + threadIdx.x; i < n; i += gridDim.x*blockDim.x) {
        g_h[i] = 0.0f;
        if (i < n/2) ((uint32_t*)g_hf)[i] = 0u;
    }
}

// ---------------- fused per-timestep kernel ----------------
__global__ void __launch_bounds__(NTHREADS)
gru_step(const float* __restrict__ bF, const float* __restrict__ bB,
         float* __restrict__ out, int s)
{
    extern __shared__ char smc[];
    char*  sHalo = smc;
    char*  sWA   = smc + SM_HALO_B;
    char*  sWB   = sWA + SM_WA_B;
    float* sZ    = (float*)(smc + SM_Z_OFF);

    const int dir = blockIdx.y, tile = blockIdx.x;
    const int ty0 = (tile / 10) * TILY, tx0 = (tile % 10) * TILX;
    const int t   = dir ? (TT - 1 - s) : s;
    const int tid = threadIdx.x;
    const float* bias = dir ? bB : bF;

    // both weight sets -> smem
    {
        const uint4* srcA = (const uint4*)(g_wAh + (size_t)dir*64*KW);
        uint4* dA = (uint4*)sWA;
        for (int i = tid; i < SM_WA_B/16; i += NTHREADS) dA[i] = srcA[i];
        const uint4* srcB = (const uint4*)(g_wBh + (size_t)dir*32*KW);
        uint4* dB = (uint4*)sWB;
        for (int i = tid; i < SM_WB_B/16; i += NTHREADS) dB[i] = srcB[i];
    }
    // stage +-2 region, both batches (768 px)
    for (int u = tid; u < 2*NSTG; u += NTHREADS) {
        int hb = u / NSTG, p = u - hb*NSTG;
        int sy = p >> 4, sx = p & 15;
        int gy = ty0 + sy - 2, gx = tx0 + sx - 2;
        uint4* dst = (uint4*)(sHalo + u*PXB);
        if (gy >= 0 && gy < HH && gx >= 0 && gx < WW) {
            const uint4* hs = (const uint4*)(g_hf + (size_t)((dir*2 + hb)*NPX + gy*WW + gx)*FF);
            dst[0] = hs[0]; dst[1] = hs[1]; dst[2] = hs[2]; dst[3] = hs[3];
            dst[4] = *(const uint4*)(g_xf8 + (size_t)((hb*TT + t)*NPX + gy*WW + gx)*8);
            dst[5] = make_uint4(0u,0u,0u,0u);
            dst[6] = make_uint4(0u,0u,0u,0u);
        } else {
            uint4 z = make_uint4(0u,0u,0u,0u);
            #pragma unroll
            for (int j = 0; j < 7; ++j) dst[j] = z;
        }
    }
    __syncthreads();

    const int warp = tid >> 5, lane = tid & 31;
    const int wb = warp / 10, wl = warp - wb*10;   // batch, warp-in-batch (phase A)
    const uint32_t haloAll = smem_u32(sHalo);
    const int fc = (lane & 3) * 2;
    const uint32_t aHalf = (uint32_t)((lane >> 4) << 4);

    // ======================= Phase A: gates on ring =======================
    uint32_t rbA[2];
    #pragma unroll
    for (int si = 0; si < 2; ++si) {
        int m = (wl + si*10)*16 + (lane & 15);
        int q = m / RINGW;
        int sy = (m < NRING) ? 1 + q : 1;
        int sx = (m < NRING) ? 1 + m - q*RINGW : 1;
        rbA[si] = haloAll + (uint32_t)((wb*NSTG + sy*SGX + sx)*PXB) + aHalf;
    }
    const uint32_t bThrA = smem_u32(sWA) + (uint32_t)(((lane>>4)*8 + (lane&7))*WRB)
                                         + (uint32_t)(((lane>>3)&1) << 4);

    float C0[8][4], C1[8][4];
    #pragma unroll
    for (int j = 0; j < 8; ++j) {
        C0[j][0]=C0[j][1]=C0[j][2]=C0[j][3]=0.0f;
        C1[j][0]=C1[j][1]=C1[j][2]=C1[j][3]=0.0f;
    }

    #pragma unroll
    for (int ky = 0; ky < 3; ++ky)
    #pragma unroll
    for (int kx = 0; kx < 3; ++kx) {
        const int tap = ky*3 + kx;
        const int po  = ((ky-1)*SGX + (kx-1))*PXB;
        #pragma unroll
        for (int ch = 0; ch < 3; ++ch) {
            uint32_t a00,a01,a02,a03, a10,a11,a12,a13;
            ldm_x4(a00,a01,a02,a03, rbA[0] + po + ch*32);
            ldm_x4(a10,a11,a12,a13, rbA[1] + po + ch*32);
            const uint32_t bt = bThrA + (uint32_t)(tap*96 + ch*32);
            #pragma unroll
            for (int jp = 0; jp < 4; ++jp) {
                uint32_t b0,b1,b2,b3;
                ldm_x4(b0,b1,b2,b3, bt + (uint32_t)(jp*16*WRB));
                mma16816(C0[2*jp],   a00,a01,a02,a03, b0,b1);
                mma16816(C0[2*jp+1], a00,a01,a02,a03, b2,b3);
                mma16816(C1[2*jp],   a10,a11,a12,a13, b0,b1);
                mma16816(C1[2*jp+1], a10,a11,a12,a13, b2,b3);
            }
        }
    }

    // epilogue A: z -> sZ (fp32, interior only); rh buffered, then written
    uint32_t rhOff[2][2];       // byte offset of pixel in sHalo
    uint32_t rhV[2][2][4];      // half2 rh values
    int      rhReal[2][2];
    #pragma unroll
    for (int si = 0; si < 2; ++si) {
        float (*C)[4] = si ? C1 : C0;
        #pragma unroll
        for (int cc = 0; cc < 2; ++cc) {
            int m = (wl + si*10)*16 + 8*cc + (lane >> 2);
            int real = (m < NRING);
            int q = m / RINGW;
            int sy = real ? 1 + q : 1;
            int sx = real ? 1 + m - q*RINGW : 1;
            uint32_t off = (uint32_t)((wb*NSTG + sy*SGX + sx)*PXB);
            rhOff[si][cc] = off; rhReal[si][cc] = real;
            if (real && sy >= 2 && sy < 22 && sx >= 2 && sx < 14) {
                int mi = (sy-2)*TILX + (sx-2);
                float* zp = sZ + (size_t)(wb*NINT + mi)*32;
                #pragma unroll
                for (int j = 0; j < 4; ++j) {
                    int n = j*8 + fc;
                    float v0 = sigm(C[j][2*cc]   + __ldg(bias + n));
                    float v1 = sigm(C[j][2*cc+1] + __ldg(bias + n + 1));
                    *(float2*)(zp + n) = make_float2(v0, v1);
                }
            }
            #pragma unroll
            for (int jj = 0; jj < 4; ++jj) {
                int n = 32 + jj*8 + fc;
                float r0 = sigm(C[jj+4][2*cc]   + __ldg(bias + n));
                float r1 = sigm(C[jj+4][2*cc+1] + __ldg(bias + n + 1));
                float2 hv = __half22float2(*(__half2*)(sHalo + off + (jj*8 + fc)*2));
                __half2 rh = __floats2half2_rn(r0*hv.x, r1*hv.y);
                rhV[si][cc][jj] = *(uint32_t*)&rh;
            }
        }
    }
    __syncthreads();   // everyone done READING h from halo
    #pragma unroll
    for (int si = 0; si < 2; ++si)
    #pragma unroll
    for (int cc = 0; cc < 2; ++cc) {
        if (rhReal[si][cc]) {
            #pragma unroll
            for (int jj = 0; jj < 4; ++jj)
                *(uint32_t*)(sHalo + rhOff[si][cc] + (jj*8 + fc)*2) = rhV[si][cc][jj];
        }
    }
    __syncthreads();   // rh visible

    // ======================= Phase B: candidate on interior =======================
    const bool has2 = (warp < 10);
    uint32_t rbB[2]; int batB[2], slB[2];
    #pragma unroll
    for (int si = 0; si < 2; ++si) {
        int sg = (si == 0) ? warp : (has2 ? warp + 20 : warp);
        int bb = sg / 15, sl = sg - bb*15;
        batB[si] = bb; slB[si] = sl;
        int m = sl*16 + (lane & 15);
        int q = m / TILX;
        int sy = 2 + q, sx = 2 + m - q*TILX;
        rbB[si] = haloAll + (uint32_t)((bb*NSTG + sy*SGX + sx)*PXB) + aHalf;
    }
    const uint32_t bThrB = smem_u32(sWB) + (uint32_t)(((lane>>4)*8 + (lane&7))*WRB)
                                         + (uint32_t)(((lane>>3)&1) << 4);

    float D0[4][4], D1[4][4];
    #pragma unroll
    for (int j = 0; j < 4; ++j) {
        D0[j][0]=D0[j][1]=D0[j][2]=D0[j][3]=0.0f;
        D1[j][0]=D1[j][1]=D1[j][2]=D1[j][3]=0.0f;
    }

    #pragma unroll
    for (int ky = 0; ky < 3; ++ky)
    #pragma unroll
    for (int kx = 0; kx < 3; ++kx) {
        const int tap = ky*3 + kx;
        const int po  = ((ky-1)*SGX + (kx-1))*PXB;
        #pragma unroll
        for (int ch = 0; ch < 3; ++ch) {
            uint32_t a00,a01,a02,a03, a10,a11,a12,a13;
            ldm_x4(a00,a01,a02,a03, rbB[0] + po + ch*32);
            ldm_x4(a10,a11,a12,a13, rbB[1] + po + ch*32);
            const uint32_t bt = bThrB + (uint32_t)(tap*96 + ch*32);
            #pragma unroll
            for (int jp = 0; jp < 2; ++jp) {
                uint32_t b0,b1,b2,b3;
                ldm_x4(b0,b1,b2,b3, bt + (uint32_t)(jp*16*WRB));
                mma16816(D0[2*jp],   a00,a01,a02,a03, b0,b1);
                mma16816(D0[2*jp+1], a00,a01,a02,a03, b2,b3);
                mma16816(D1[2*jp],   a10,a11,a12,a13, b0,b1);
                mma16816(D1[2*jp+1], a10,a11,a12,a13, b2,b3);
            }
        }
    }

    // epilogue B: GRU update, write h (fp32), hf (f16), out
    #pragma unroll
    for (int si = 0; si < 2; ++si) {
        if (si == 1 && !has2) break;
        float (*D)[4] = si ? D1 : D0;
        const int bb = batB[si], sl = slB[si];
        #pragma unroll
        for (int cc = 0; cc < 2; ++cc) {
            int m = sl*16 + 8*cc + (lane >> 2);
            int q = m / TILX;
            int sy = 2 + q, sx = 2 + m - q*TILX;
            int gy = ty0 + sy - 2, gx = tx0 + sx - 2;
            const size_t pb = (size_t)((dir*2 + bb)*NPX + gy*WW + gx)*FF;
            const float* zp = sZ + (size_t)(bb*NINT + m)*32;
            float* op = out + ((size_t)((bb*TT + t)*HH + gy)*WW + gx)*64 + dir*32;
            #pragma unroll
            for (int j = 0; j < 4; ++j) {
                int n = j*8 + fc;
                float2 z = *(const float2*)(zp + n);
                float2 h = *(const float2*)(g_h + pb + n);
                float hh0 = ftanh(D[j][2*cc]   + __ldg(bias + 64 + n));
                float hh1 = ftanh(D[j][2*cc+1] + __ldg(bias + 64 + n + 1));
                float2 hn = make_float2(z.x*h.x + (1.0f - z.x)*hh0,
                                        z.y*h.y + (1.0f - z.y)*hh1);
                *(float2*)(g_h + pb + n)   = hn;
                *(__half2*)(g_hf + pb + n) = __floats2half2_rn(hn.x, hn.y);
                *(float2*)(op + n)         = hn;
            }
        }
    }
}

extern "C" void kernel_launch(void* const* d_in, const int* in_sizes, int n_in,
                              void* d_out, int out_size)
{
    const float* x    = (const float*)d_in[0];
    const float* WxF  = (const float*)d_in[1];
    const float* bF   = (const float*)d_in[2];
    const float* WzrF = (const float*)d_in[3];
    const float* WhF  = (const float*)d_in[4];
    const float* WxB  = (const float*)d_in[5];
    const float* bB   = (const float*)d_in[6];
    const float* WzrB = (const float*)d_in[7];
    const float* WhB  = (const float*)d_in[8];
    float* out = (float*)d_out;

    cudaFuncSetAttribute(gru_step, cudaFuncAttributeMaxDynamicSharedMemorySize, SM_TOTAL);

    pack_kernel<<<96, 256>>>(WxF, WzrF, WhF, WxB, WzrB, WhB);
    convert_x_kernel<<<256, 256>>>(x);
    zero_h_kernel<<<256, 256>>>();

    dim3 grid(NTILES, 2);   // 40 tiles x 2 dir = 80 blocks (single wave)
    for (int s = 0; s < TT; ++s)
        gru_step<<<grid, NTHREADS, SM_TOTAL>>>(bF, bB, out, s);
}

// round 11
// speedup vs baseline: 1.3575x; 1.3575x over previous
#include <cuda_runtime.h>
#include <cuda_fp16.h>
#include <cstdint>

// ---------------- problem constants ----------------
#define HH 80
#define WW 120
#define TT 12
#define FF 32
#define NPX (HH*WW)

#define TILY 20
#define TILX 8
#define NTILES 60        // (80/20) * (120/8)
#define NTHREADS 640     // 20 warps: 10 row-groups (5/batch) x 2 n-slices

#define HROWS 22
#define HCOLS 10
#define NHALO 220        // halo pixels per batch
#define PXB 112          // pixel stride bytes: [h 32f16 | x 8f16 | pad]

#define KW 440           // f16 per weight row (432 = 9*48 + pad)
#define WRB 880

#define SM_HALO_B (2*NHALO*PXB)   // 49280
#define SM_WA_B   (64*WRB)        // 56320
#define SM_WB_B   (32*WRB)        // 28160

// ---------------- global scratch ----------------
__device__ __half g_wAh[2*64*KW];
__device__ __half g_wBh[2*32*KW];
__device__ float  g_h  [2*2*NPX*FF];     // fp32 state (exact bypass)
__device__ float  g_z  [2*2*NPX*FF];     // fp32 update gate
__device__ __half g_hf [2*2*NPX*FF];     // f16 mirror (conv operand)
__device__ __half g_rhf[2*2*NPX*FF];     // f16 r*h (conv operand)
__device__ __half g_xf8[2*TT*NPX*8];     // x preconverted (6 + 2 zeros)

// ---------------- helpers ----------------
__device__ __forceinline__ uint32_t smem_u32(const void* p) {
    uint32_t a;
    asm("{ .reg .u64 t; cvta.to.shared.u64 t, %1; cvt.u32.u64 %0, t; }" : "=r"(a) : "l"(p));
    return a;
}
__device__ __forceinline__ float sigm(float v) {
    return __fdividef(1.0f, 1.0f + __expf(-v));
}
__device__ __forceinline__ float ftanh(float v) {
    float e = __expf(-2.0f * v);
    return __fdividef(1.0f - e, 1.0f + e);
}
__device__ __forceinline__ void ldm_x4(uint32_t& r0, uint32_t& r1, uint32_t& r2, uint32_t& r3,
                                       uint32_t addr) {
    asm volatile("ldmatrix.sync.aligned.m8n8.x4.shared.b16 {%0,%1,%2,%3}, [%4];"
                 : "=r"(r0), "=r"(r1), "=r"(r2), "=r"(r3) : "r"(addr));
}
__device__ __forceinline__ void mma16816(float* c,
                                         uint32_t a0, uint32_t a1, uint32_t a2, uint32_t a3,
                                         uint32_t b0, uint32_t b1) {
    asm volatile("mma.sync.aligned.m16n8k16.row.col.f32.f16.f16.f32 "
                 "{%0,%1,%2,%3}, {%4,%5,%6,%7}, {%8,%9}, {%0,%1,%2,%3};"
                 : "+f"(c[0]), "+f"(c[1]), "+f"(c[2]), "+f"(c[3])
                 : "r"(a0), "r"(a1), "r"(a2), "r"(a3), "r"(b0), "r"(b1));
}

// ---------------- one-time packs ----------------
__global__ void pack_kernel(const float* __restrict__ WxF, const float* __restrict__ WzrF,
                            const float* __restrict__ WhF,
                            const float* __restrict__ WxB, const float* __restrict__ WzrB,
                            const float* __restrict__ WhB)
{
    const int TOT = 2*96*KW;
    for (int i = blockIdx.x*blockDim.x + threadIdx.x; i < TOT; i += gridDim.x*blockDim.x) {
        int dir = i / (96*KW); int r = i - dir*(96*KW);
        int n96 = r / KW;      int k = r - n96*KW;
        float v = 0.0f;
        if (k < 432) {
            int tap = k / 48, c = k - tap*48;
            const float* Wx  = dir ? WxB  : WxF;
            const float* Wzr = dir ? WzrB : WzrF;
            const float* Wh  = dir ? WhB  : WhF;
            if (c < 32) {
                if (n96 < 64) v = Wzr[(tap*32 + c)*64 + n96];
                else          v = Wh [(tap*32 + c)*32 + (n96 - 64)];
            } else if (c < 38) {
                v = Wx[(tap*6 + (c - 32))*96 + n96];
            }
        }
        __half hv = __float2half_rn(v);
        if (n96 < 64) g_wAh[(dir*64 + n96)*KW + k]        = hv;
        else          g_wBh[(dir*32 + (n96 - 64))*KW + k] = hv;
    }
}

__global__ void convert_x_kernel(const float* __restrict__ x) {
    const int n = 2*TT*NPX;
    for (int p = blockIdx.x*blockDim.x + threadIdx.x; p < n; p += gridDim.x*blockDim.x) {
        const float* src = x + (size_t)p*6;
        __half2 h0 = __floats2half2_rn(src[0], src[1]);
        __half2 h1 = __floats2half2_rn(src[2], src[3]);
        __half2 h2 = __floats2half2_rn(src[4], src[5]);
        uint4 v;
        v.x = *(uint32_t*)&h0; v.y = *(uint32_t*)&h1; v.z = *(uint32_t*)&h2; v.w = 0u;
        *(uint4*)(g_xf8 + (size_t)p*8) = v;
    }
}

__global__ void zero_h_kernel() {
    const int n = 2*2*NPX*FF;
    for (int i = blockIdx.x*blockDim.x + threadIdx.x; i < n; i += gridDim.x*blockDim.x) {
        g_h[i] = 0.0f;
        if (i < n/2) ((uint32_t*)g_hf)[i] = 0u;
    }
}

// ---------------- halo staging: aligned f16 copies ----------------
__device__ __forceinline__ void stage_halo(char* sHalo, const __half* __restrict__ stf,
                                           int dir, int t, int ty0, int tx0, int tid)
{
    if (tid < 2*NHALO) {
        const int hb  = tid / NHALO;
        const int hpx = tid - hb*NHALO;
        const int sy = hpx / HCOLS, sx = hpx - sy*HCOLS;
        const int gy = ty0 + sy - 1, gx = tx0 + sx - 1;
        uint4* dst = (uint4*)(sHalo + tid*PXB);
        if (gy >= 0 && gy < HH && gx >= 0 && gx < WW) {
            const uint4* hs = (const uint4*)(stf + (size_t)((dir*2 + hb)*NPX + gy*WW + gx)*FF);
            dst[0] = hs[0]; dst[1] = hs[1]; dst[2] = hs[2]; dst[3] = hs[3];
            dst[4] = *(const uint4*)(g_xf8 + (size_t)((hb*TT + t)*NPX + gy*WW + gx)*8);
            dst[5] = make_uint4(0u,0u,0u,0u);
            dst[6] = make_uint4(0u,0u,0u,0u);
        } else {
            uint4 z = make_uint4(0u,0u,0u,0u);
            #pragma unroll
            for (int j = 0; j < 7; ++j) dst[j] = z;
        }
    }
}

// ---------------- Kernel A: gates (software-pipelined, r32 x n32 per warp) ---------
__global__ void __launch_bounds__(NTHREADS, 1)
stepA(const float* __restrict__ bF, const float* __restrict__ bB, int s)
{
    extern __shared__ char smc[];
    char* sHalo = smc;
    char* sW    = smc + SM_HALO_B;

    const int dir = blockIdx.y, tile = blockIdx.x;
    const int ty0 = (tile / 15) * TILY, tx0 = (tile % 15) * TILX;
    const int t   = dir ? (TT - 1 - s) : s;
    const int tid = threadIdx.x;
    const float* bias = dir ? bB : bF;

    {
        const uint4* src = (const uint4*)(g_wAh + (size_t)dir*64*KW);
        uint4* dst = (uint4*)sW;
        for (int i = tid; i < SM_WA_B/16; i += NTHREADS) dst[i] = src[i];
    }
    stage_halo(sHalo, g_hf, dir, t, ty0, tx0, tid);
    __syncthreads();

    const int warp = tid >> 5, lane = tid & 31;
    const int rg5 = warp % 10;           // row-group (5 per batch)
    const int nh  = warp / 10;           // n-slice: 0 -> z, 1 -> r
    const int wb  = rg5 / 5;             // batch
    const int rgl = rg5 % 5;             // row-group in batch (4 rows of 8 px)
    const uint32_t haloB = smem_u32(sHalo) + (uint32_t)(wb*NHALO*PXB);
    const uint32_t aHalf = (uint32_t)((lane >> 4) << 4);

    uint32_t rb[2];
    #pragma unroll
    for (int si = 0; si < 2; ++si) {
        int r  = lane & 15;
        int py = 4*rgl + 2*si + (r >> 3);
        int px = r & 7;
        rb[si] = haloB + (uint32_t)((py*HCOLS + px)*PXB) + aHalf;
    }
    const uint32_t wB0 = smem_u32(sW);
    uint32_t bt[2];
    #pragma unroll
    for (int jp = 0; jp < 2; ++jp)
        bt[jp] = wB0 + (uint32_t)(((nh*32 + jp*16 + (lane>>4)*8 + (lane&7))*WRB))
                     + (uint32_t)(((lane>>3)&1) << 4);

    float C[2][4][4];
    #pragma unroll
    for (int si = 0; si < 2; ++si)
        #pragma unroll
        for (int j = 0; j < 4; ++j)
            C[si][j][0]=C[si][j][1]=C[si][j][2]=C[si][j][3]=0.0f;

    uint32_t Af[2][2][4], Bf[2][2][4];
    // prologue: kstep 0 (tap 0, ch 0)
    ldm_x4(Af[0][0][0],Af[0][0][1],Af[0][0][2],Af[0][0][3], rb[0]);
    ldm_x4(Af[0][1][0],Af[0][1][1],Af[0][1][2],Af[0][1][3], rb[1]);
    ldm_x4(Bf[0][0][0],Bf[0][0][1],Bf[0][0][2],Bf[0][0][3], bt[0]);
    ldm_x4(Bf[0][1][0],Bf[0][1][1],Bf[0][1][2],Bf[0][1][3], bt[1]);

    #pragma unroll
    for (int kk = 0; kk < 27; ++kk) {
        const int cur = kk & 1, nxt = cur ^ 1;
        if (kk < 26) {
            const int k1  = kk + 1;
            const int tap = k1 / 3, ch = k1 - tap*3;
            const int ky  = tap / 3, kx = tap - ky*3;
            const uint32_t po = (uint32_t)((ky*HCOLS + kx)*PXB + ch*32);
            const uint32_t wo = (uint32_t)(tap*96 + ch*32);
            ldm_x4(Af[nxt][0][0],Af[nxt][0][1],Af[nxt][0][2],Af[nxt][0][3], rb[0] + po);
            ldm_x4(Af[nxt][1][0],Af[nxt][1][1],Af[nxt][1][2],Af[nxt][1][3], rb[1] + po);
            ldm_x4(Bf[nxt][0][0],Bf[nxt][0][1],Bf[nxt][0][2],Bf[nxt][0][3], bt[0] + wo);
            ldm_x4(Bf[nxt][1][0],Bf[nxt][1][1],Bf[nxt][1][2],Bf[nxt][1][3], bt[1] + wo);
        }
        #pragma unroll
        for (int si = 0; si < 2; ++si)
            #pragma unroll
            for (int jp = 0; jp < 2; ++jp) {
                mma16816(C[si][2*jp],
                         Af[cur][si][0],Af[cur][si][1],Af[cur][si][2],Af[cur][si][3],
                         Bf[cur][jp][0],Bf[cur][jp][1]);
                mma16816(C[si][2*jp+1],
                         Af[cur][si][0],Af[cur][si][1],Af[cur][si][2],Af[cur][si][3],
                         Bf[cur][jp][2],Bf[cur][jp][3]);
            }
    }

    // epilogue: nh=0 -> z (fp32), nh=1 -> r*h (f16 mirror)
    const int fc  = (lane & 3) * 2;
    const int pxe = lane >> 2;
    const size_t sob = (size_t)(dir*2 + wb)*NPX*FF;
    #pragma unroll
    for (int si = 0; si < 2; ++si)
    #pragma unroll
    for (int cc = 0; cc < 2; ++cc) {
        const int py = 4*rgl + 2*si + cc;
        const int gy = ty0 + py, gx = tx0 + pxe;
        const size_t pb = sob + (size_t)(gy*WW + gx)*FF;
        if (nh == 0) {
            #pragma unroll
            for (int j = 0; j < 4; ++j) {
                const int n = j*8 + fc;
                float v0 = sigm(C[si][j][2*cc]   + __ldg(bias + n));
                float v1 = sigm(C[si][j][2*cc+1] + __ldg(bias + n + 1));
                *(float2*)(g_z + pb + n) = make_float2(v0, v1);
            }
        } else {
            const char* hpx = sHalo + (size_t)(wb*NHALO + (py+1)*HCOLS + (pxe+1))*PXB;
            #pragma unroll
            for (int j = 0; j < 4; ++j) {
                const int n = j*8 + fc;
                float r0 = sigm(C[si][j][2*cc]   + __ldg(bias + 32 + n));
                float r1 = sigm(C[si][j][2*cc+1] + __ldg(bias + 32 + n + 1));
                float2 hv = __half22float2(*(const __half2*)(hpx + n*2));
                *(__half2*)(g_rhf + pb + n) = __floats2half2_rn(r0*hv.x, r1*hv.y);
            }
        }
    }
}

// ---------------- Kernel B: candidate + GRU update (pipelined, r32 x n16) ----------
__global__ void __launch_bounds__(NTHREADS, 1)
stepB(const float* __restrict__ bF, const float* __restrict__ bB,
      float* __restrict__ out, int s)
{
    extern __shared__ char smc[];
    char* sHalo = smc;
    char* sW    = smc + SM_HALO_B;

    const int dir = blockIdx.y, tile = blockIdx.x;
    const int ty0 = (tile / 15) * TILY, tx0 = (tile % 15) * TILX;
    const int t   = dir ? (TT - 1 - s) : s;
    const int tid = threadIdx.x;
    const float* bias = dir ? bB : bF;

    {
        const uint4* src = (const uint4*)(g_wBh + (size_t)dir*32*KW);
        uint4* dst = (uint4*)sW;
        for (int i = tid; i < SM_WB_B/16; i += NTHREADS) dst[i] = src[i];
    }
    stage_halo(sHalo, g_rhf, dir, t, ty0, tx0, tid);
    __syncthreads();

    const int warp = tid >> 5, lane = tid & 31;
    const int rg5 = warp % 10;
    const int nh  = warp / 10;           // n-slice: channels [nh*16, nh*16+16)
    const int wb  = rg5 / 5;
    const int rgl = rg5 % 5;
    const uint32_t haloB = smem_u32(sHalo) + (uint32_t)(wb*NHALO*PXB);
    const uint32_t aHalf = (uint32_t)((lane >> 4) << 4);

    uint32_t rb[2];
    #pragma unroll
    for (int si = 0; si < 2; ++si) {
        int r  = lane & 15;
        int py = 4*rgl + 2*si + (r >> 3);
        int px = r & 7;
        rb[si] = haloB + (uint32_t)((py*HCOLS + px)*PXB) + aHalf;
    }
    const uint32_t wB0 = smem_u32(sW);
    const uint32_t bt = wB0 + (uint32_t)(((nh*16 + (lane>>4)*8 + (lane&7))*WRB))
                           + (uint32_t)(((lane>>3)&1) << 4);

    float C[2][2][4];
    #pragma unroll
    for (int si = 0; si < 2; ++si)
        #pragma unroll
        for (int j = 0; j < 2; ++j)
            C[si][j][0]=C[si][j][1]=C[si][j][2]=C[si][j][3]=0.0f;

    uint32_t Af[2][2][4], Bf[2][4];
    ldm_x4(Af[0][0][0],Af[0][0][1],Af[0][0][2],Af[0][0][3], rb[0]);
    ldm_x4(Af[0][1][0],Af[0][1][1],Af[0][1][2],Af[0][1][3], rb[1]);
    ldm_x4(Bf[0][0],Bf[0][1],Bf[0][2],Bf[0][3], bt);

    #pragma unroll
    for (int kk = 0; kk < 27; ++kk) {
        const int cur = kk & 1, nxt = cur ^ 1;
        if (kk < 26) {
            const int k1  = kk + 1;
            const int tap = k1 / 3, ch = k1 - tap*3;
            const int ky  = tap / 3, kx = tap - ky*3;
            const uint32_t po = (uint32_t)((ky*HCOLS + kx)*PXB + ch*32);
            const uint32_t wo = (uint32_t)(tap*96 + ch*32);
            ldm_x4(Af[nxt][0][0],Af[nxt][0][1],Af[nxt][0][2],Af[nxt][0][3], rb[0] + po);
            ldm_x4(Af[nxt][1][0],Af[nxt][1][1],Af[nxt][1][2],Af[nxt][1][3], rb[1] + po);
            ldm_x4(Bf[nxt][0],Bf[nxt][1],Bf[nxt][2],Bf[nxt][3], bt + wo);
        }
        #pragma unroll
        for (int si = 0; si < 2; ++si) {
            mma16816(C[si][0],
                     Af[cur][si][0],Af[cur][si][1],Af[cur][si][2],Af[cur][si][3],
                     Bf[cur][0],Bf[cur][1]);
            mma16816(C[si][1],
                     Af[cur][si][0],Af[cur][si][1],Af[cur][si][2],Af[cur][si][3],
                     Bf[cur][2],Bf[cur][3]);
        }
    }

    // epilogue: GRU update
    const int fc  = (lane & 3) * 2;
    const int pxe = lane >> 2;
    const size_t sob = (size_t)(dir*2 + wb)*NPX*FF;
    #pragma unroll
    for (int si = 0; si < 2; ++si)
    #pragma unroll
    for (int cc = 0; cc < 2; ++cc) {
        const int py = 4*rgl + 2*si + cc;
        const int gy = ty0 + py, gx = tx0 + pxe;
        const size_t pb = sob + (size_t)(gy*WW + gx)*FF;
        float* op = out + ((size_t)((wb*TT + t)*HH + gy)*WW + gx)*64 + dir*32;
        #pragma unroll
        for (int j = 0; j < 2; ++j) {
            const int n = nh*16 + j*8 + fc;
            float2 z = *(const float2*)(g_z + pb + n);
            float2 h = *(const float2*)(g_h + pb + n);
            float hh0 = ftanh(C[si][j][2*cc]   + __ldg(bias + 64 + n));
            float hh1 = ftanh(C[si][j][2*cc+1] + __ldg(bias + 64 + n + 1));
            float2 hn = make_float2(z.x*h.x + (1.0f - z.x)*hh0,
                                    z.y*h.y + (1.0f - z.y)*hh1);
            *(float2*)(g_h + pb + n)   = hn;
            *(__half2*)(g_hf + pb + n) = __floats2half2_rn(hn.x, hn.y);
            *(float2*)(op + n)         = hn;
        }
    }
}

extern "C" void kernel_launch(void* const* d_in, const int* in_sizes, int n_in,
                              void* d_out, int out_size)
{
    const float* x    = (const float*)d_in[0];
    const float* WxF  = (const float*)d_in[1];
    const float* bF   = (const float*)d_in[2];
    const float* WzrF = (const float*)d_in[3];
    const float* WhF  = (const float*)d_in[4];
    const float* WxB  = (const float*)d_in[5];
    const float* bB   = (const float*)d_in[6];
    const float* WzrB = (const float*)d_in[7];
    const float* WhB  = (const float*)d_in[8];
    float* out = (float*)d_out;

    const int smA = SM_HALO_B + SM_WA_B;   // 105600 B
    const int smB = SM_HALO_B + SM_WB_B;   // 77440 B
    cudaFuncSetAttribute(stepA, cudaFuncAttributeMaxDynamicSharedMemorySize, smA);
    cudaFuncSetAttribute(stepB, cudaFuncAttributeMaxDynamicSharedMemorySize, smB);

    pack_kernel<<<96, 256>>>(WxF, WzrF, WhF, WxB, WzrB, WhB);
    convert_x_kernel<<<256, 256>>>(x);
    zero_h_kernel<<<256, 256>>>();

    dim3 grid(NTILES, 2);   // 60 tiles x 2 dir = 120 blocks (single wave)
    for (int s = 0; s < TT; ++s) {
        stepA<<<grid, NTHREADS, smA>>>(bF, bB, s);
        stepB<<<grid, NTHREADS, smB>>>(bF, bB, out, s);
    }
}